// round 7
// baseline (speedup 1.0000x reference)
#include <cuda_runtime.h>
#include <cuda_bf16.h>
#include <cstdint>

// SPLoPAdapter as ONE GEMM:
//   delta2[ij, ab] = sum_k pos[k, ij] * G[ab, k],  G[ab,k] = w[k,a]*h[k,b]
//   out[i*32+a, j*32+b] = weights[...] + delta2[i*64+j, a*32+b]
// M=4096(ij) x N=1024(ab) x K=64, bf16 mma.sync m16n8k16, fp32 accum.
// CTA: 256 thr, tile 128(ij) x 64(ab)  ==  4 complete output rows of 2048.
// Epilogue: frags -> swizzled smem delta[4][2048] -> coalesced LDG/STG.128.

static constexpr int ASW = 36;   // As row stride in u32 words
static constexpr int BSW = 36;   // Bt row stride in u32 words
static constexpr int HST = 33;   // h_s row stride in floats

// smem byte offsets (delta[4][2048] fp32 = 32 KB reuses the staging region)
static constexpr int OFF_AS = 0;
static constexpr int OFF_BT = OFF_AS + 128 * ASW * 4;   // 18432
static constexpr int OFF_H  = OFF_BT + 64 * BSW * 4;    // 27648
static constexpr int OFF_W  = OFF_H + 64 * HST * 4;     // 36096
static constexpr int SMEM_BYTES = OFF_W + 512;          // 36608

__device__ __forceinline__ void mma_bf16(float* d, const uint32_t* a, const uint32_t* b) {
    asm volatile(
        "mma.sync.aligned.m16n8k16.row.col.f32.bf16.bf16.f32 "
        "{%0,%1,%2,%3}, {%4,%5,%6,%7}, {%8,%9}, {%0,%1,%2,%3};"
        : "+f"(d[0]), "+f"(d[1]), "+f"(d[2]), "+f"(d[3])
        : "r"(a[0]), "r"(a[1]), "r"(a[2]), "r"(a[3]), "r"(b[0]), "r"(b[1]));
}

__device__ __forceinline__ uint32_t packbf(float f0, float f1) {
    __nv_bfloat162 p = __floats2bfloat162_rn(f0, f1);  // low=f0(k), high=f1(k+1)
    return *(uint32_t*)&p;
}

__global__ void __launch_bounds__(256, 3) splopa_mma_kernel(
    const float* __restrict__ weights,
    const float* __restrict__ pos,
    const float* __restrict__ pw,
    const float* __restrict__ ph,
    float* __restrict__ out)
{
    __shared__ __align__(16) char smem[SMEM_BYTES];
    uint32_t* As32  = (uint32_t*)(smem + OFF_AS);
    uint32_t* Bt32  = (uint32_t*)(smem + OFF_BT);
    float*    h_s   = (float*)(smem + OFF_H);
    float*    w_s   = (float*)(smem + OFF_W);
    float*    delta = (float*)smem;            // [4][2048], reused after main loop

    const int tid  = threadIdx.x;
    const int wid  = tid >> 5;
    const int lane = tid & 31;
    const int g    = lane >> 2;    // 0..7
    const int tig  = lane & 3;     // 0..3

    const int bx = blockIdx.x;          // ab block: a in {2bx, 2bx+1}
    const int by = blockIdx.y;          // ij block: 128 ij
    const int ab0 = bx * 64;
    const int ij0 = by * 128;

    // ---- stage h (padded) ----
    #pragma unroll
    for (int it = 0; it < 8; it++) {
        const int idx = tid + it * 256;
        h_s[(idx >> 5) * HST + (idx & 31)] = ph[idx];
    }
    // ---- stage w slice (2 a-columns) ----
    if (tid < 128)
        w_s[tid] = pw[(tid >> 1) * 32 + (ab0 >> 5) + (tid & 1)];

    // ---- stage As[ij][kw]: column reads, STS.128 quads ----
    {
        const int ijl  = tid & 127;
        const int qsel = tid >> 7;
        const float* pb = pos + ij0 + ijl;
        #pragma unroll
        for (int qq = 0; qq < 4; qq++) {
            const int q = qsel * 4 + qq;
            uint32_t pk[4];
            #pragma unroll
            for (int e = 0; e < 4; e++) {
                const float f0 = pb[(size_t)(8 * q + 2 * e) * 4096];
                const float f1 = pb[(size_t)(8 * q + 2 * e + 1) * 4096];
                pk[e] = packbf(f0, f1);
            }
            *(uint4*)&As32[ijl * ASW + 4 * q] = make_uint4(pk[0], pk[1], pk[2], pk[3]);
        }
    }
    __syncthreads();

    // ---- build Bt[ab][kw] = bf16x2(w[k,a]*h[k,b]) ----
    {
        const int ab   = tid >> 2;
        const int asel = ab >> 5;
        const int bsel = ab & 31;
        #pragma unroll
        for (int qi = 0; qi < 2; qi++) {
            const int q = (tid & 3) * 2 + qi;
            uint32_t pk[4];
            #pragma unroll
            for (int e = 0; e < 4; e++) {
                const int k = 8 * q + 2 * e;
                const float f0 = w_s[k * 2 + asel]       * h_s[k * HST + bsel];
                const float f1 = w_s[(k + 1) * 2 + asel] * h_s[(k + 1) * HST + bsel];
                pk[e] = packbf(f0, f1);
            }
            *(uint4*)&Bt32[ab * BSW + 4 * q] = make_uint4(pk[0], pk[1], pk[2], pk[3]);
        }
    }
    __syncthreads();

    // ---- main GEMM: warp tile 32(ij) x 32(ab) ----
    const int mw = wid >> 1;
    const int nw = wid & 1;
    const int rbase = mw * 32;
    const int cbase = nw * 32;

    float d[8][4];
    #pragma unroll
    for (int x = 0; x < 8; x++)
        #pragma unroll
        for (int c = 0; c < 4; c++)
            d[x][c] = 0.0f;

    #pragma unroll
    for (int kt = 0; kt < 4; kt++) {
        const int kw0 = kt * 8 + tig;

        uint32_t a[2][4];
        #pragma unroll
        for (int mt = 0; mt < 2; mt++) {
            const int r0 = rbase + mt * 16 + g;
            a[mt][0] = As32[r0 * ASW + kw0];
            a[mt][1] = As32[(r0 + 8) * ASW + kw0];
            a[mt][2] = As32[r0 * ASW + kw0 + 4];
            a[mt][3] = As32[(r0 + 8) * ASW + kw0 + 4];
        }

        uint32_t b[4][2];
        #pragma unroll
        for (int nt = 0; nt < 4; nt++) {
            const int col = cbase + nt * 8 + g;
            b[nt][0] = Bt32[col * BSW + kw0];
            b[nt][1] = Bt32[col * BSW + kw0 + 4];
        }

        #pragma unroll
        for (int mt = 0; mt < 2; mt++)
            #pragma unroll
            for (int nt = 0; nt < 4; nt++)
                mma_bf16(d[mt * 4 + nt], a[mt], b[nt]);
    }

    __syncthreads();   // staging smem dead; reuse as delta

    // ---- scatter fragments into delta[4][2048] (XOR-swizzled) ----
    // delta row r = i_loc*2 + a_loc; col cc = j*32 + bb; word = r*2048 + (cc ^ ((j&7)<<2))
    #pragma unroll
    for (int mt = 0; mt < 2; mt++) {
        const int ijA = rbase + mt * 16 + g;       // local ij, 0..127
        const int ijB = ijA + 8;
        #pragma unroll
        for (int nt = 0; nt < 4; nt++) {
            const int bb = nt * 8 + 2 * tig;       // 0..30 even
            const float* dd = d[mt * 4 + nt];

            const int jA = ijA & 63, rA = (ijA >> 6) * 2 + nw;
            const int wA = rA * 2048 + ((jA * 32 + bb) ^ ((jA & 7) << 2));
            *(float2*)&delta[wA] = make_float2(dd[0], dd[1]);

            const int jB = ijB & 63, rB = (ijB >> 6) * 2 + nw;
            const int wB = rB * 2048 + ((jB * 32 + bb) ^ ((jB & 7) << 2));
            *(float2*)&delta[wB] = make_float2(dd[2], dd[3]);
        }
    }
    __syncthreads();

    // ---- coalesced epilogue: 4 rows x 2048 cols ----
    // out row_g = (by*2 + i_loc)*32 + bx*2 + a_loc, cols linear
    #pragma unroll
    for (int it = 0; it < 8; it++) {
        const int idx = tid + it * 256;            // 0..2047 float4 slots
        const int r   = idx >> 9;
        const int cc  = (idx & 511) * 4;
        const int j   = cc >> 5;
        const int sw  = cc ^ ((j & 7) << 2);

        const int row_g = (by * 2 + (r >> 1)) * 32 + bx * 2 + (r & 1);
        const size_t off = (size_t)row_g * 2048 + cc;

        const float4 wv = *(const float4*)(weights + off);
        const float4 dv = *(const float4*)&delta[r * 2048 + sw];
        float4 ov;
        ov.x = wv.x + dv.x;
        ov.y = wv.y + dv.y;
        ov.z = wv.z + dv.z;
        ov.w = wv.w + dv.w;
        *(float4*)(out + off) = ov;
    }
}

extern "C" void kernel_launch(void* const* d_in, const int* in_sizes, int n_in,
                              void* d_out, int out_size)
{
    const float* weights = (const float*)d_in[0];
    const float* pos     = (const float*)d_in[1];
    const float* pw      = (const float*)d_in[2];
    const float* ph      = (const float*)d_in[3];
    float* out           = (float*)d_out;

    dim3 grid(16, 32);   // ab-blocks x ij-blocks = 512 CTAs
    dim3 block(256);
    splopa_mma_kernel<<<grid, block>>>(weights, pos, pw, ph, out);
}

// round 8
// speedup vs baseline: 1.0195x; 1.0195x over previous
#include <cuda_runtime.h>
#include <cuda_bf16.h>
#include <cstdint>

// SPLoPAdapter as ONE GEMM:
//   delta2[ij, ab] = sum_k pos[k, ij] * G[ab, k],  G[ab,k] = w[k,a]*h[k,b]
//   out[i*32+a, j*32+b] = weights[...] + delta2[i*64+j, a*32+b]
// M=4096(ij) x N=1024(ab) x K=64, bf16 mma.sync m16n8k16, fp32 accum.
// CTA: 128 thr, tile 64(ij=one i-row) x 64(ab) == 2 complete output rows.
// 8 CTAs/SM, 1024 CTAs = single wave. Epilogue via smem delta[2][2048].

static constexpr int ASW = 36;   // As row stride in u32 words
static constexpr int BSW = 36;   // Bt row stride in u32 words
static constexpr int HST = 33;   // h_s row stride in floats

static constexpr int OFF_AS = 0;
static constexpr int OFF_BT = OFF_AS + 64 * ASW * 4;    // 9216
static constexpr int OFF_H  = OFF_BT + 64 * BSW * 4;    // 18432
static constexpr int OFF_W  = OFF_H + 64 * HST * 4;     // 26880
static constexpr int SMEM_BYTES = OFF_W + 512;          // 27392 (delta 16KB reuses base)

__device__ __forceinline__ void mma_bf16(float* d, const uint32_t* a, const uint32_t* b) {
    asm volatile(
        "mma.sync.aligned.m16n8k16.row.col.f32.bf16.bf16.f32 "
        "{%0,%1,%2,%3}, {%4,%5,%6,%7}, {%8,%9}, {%0,%1,%2,%3};"
        : "+f"(d[0]), "+f"(d[1]), "+f"(d[2]), "+f"(d[3])
        : "r"(a[0]), "r"(a[1]), "r"(a[2]), "r"(a[3]), "r"(b[0]), "r"(b[1]));
}

__device__ __forceinline__ uint32_t packbf(float f0, float f1) {
    __nv_bfloat162 p = __floats2bfloat162_rn(f0, f1);
    return *(uint32_t*)&p;
}

__global__ void __launch_bounds__(128, 8) splopa_mma_kernel(
    const float* __restrict__ weights,
    const float* __restrict__ pos,
    const float* __restrict__ pw,
    const float* __restrict__ ph,
    float* __restrict__ out)
{
    __shared__ __align__(16) char smem[SMEM_BYTES];
    uint32_t* As32  = (uint32_t*)(smem + OFF_AS);
    uint32_t* Bt32  = (uint32_t*)(smem + OFF_BT);
    float*    h_s   = (float*)(smem + OFF_H);
    float*    w_s   = (float*)(smem + OFF_W);
    float*    delta = (float*)smem;        // [2][2048], reused after main loop

    const int tid  = threadIdx.x;
    const int wid  = tid >> 5;
    const int lane = tid & 31;
    const int g    = lane >> 2;    // 0..7
    const int tig  = lane & 3;     // 0..3

    const int bx = blockIdx.x;     // ab block: a in {2bx, 2bx+1}
    const int by = blockIdx.y;     // i = by, j = 0..63
    const int ab0 = bx * 64;

    // ---- stage h (padded) ----
    #pragma unroll
    for (int it = 0; it < 16; it++) {
        const int idx = tid + it * 128;
        h_s[(idx >> 5) * HST + (idx & 31)] = ph[idx];
    }
    // ---- stage w slice (2 a-columns) ----
    w_s[tid] = pw[(tid >> 1) * 32 + 2 * bx + (tid & 1)];

    // ---- stage As[j][kw]: pos column reads, STS.128 quads ----
    {
        const int jl   = tid & 63;
        const int qsel = tid >> 6;                     // 0 or 1
        const float* pb = pos + by * 64 + jl;
        #pragma unroll
        for (int qq = 0; qq < 4; qq++) {
            const int q = qsel * 4 + qq;               // kw quad: k = 8q..8q+7
            uint32_t pk[4];
            #pragma unroll
            for (int e = 0; e < 4; e++) {
                const float f0 = pb[(size_t)(8 * q + 2 * e) * 4096];
                const float f1 = pb[(size_t)(8 * q + 2 * e + 1) * 4096];
                pk[e] = packbf(f0, f1);
            }
            *(uint4*)&As32[jl * ASW + 4 * q] = make_uint4(pk[0], pk[1], pk[2], pk[3]);
        }
    }
    __syncthreads();

    // ---- build Bt[ab][kw] = bf16x2(w[k,a]*h[k,b]) ----
    {
        const int ab   = tid >> 1;        // 0..63
        const int asel = ab >> 5;
        const int bsel = ab & 31;
        #pragma unroll
        for (int qi = 0; qi < 4; qi++) {
            const int q = (tid & 1) * 4 + qi;
            uint32_t pk[4];
            #pragma unroll
            for (int e = 0; e < 4; e++) {
                const int k = 8 * q + 2 * e;
                const float f0 = w_s[k * 2 + asel]       * h_s[k * HST + bsel];
                const float f1 = w_s[(k + 1) * 2 + asel] * h_s[(k + 1) * HST + bsel];
                pk[e] = packbf(f0, f1);
            }
            *(uint4*)&Bt32[ab * BSW + 4 * q] = make_uint4(pk[0], pk[1], pk[2], pk[3]);
        }
    }
    __syncthreads();

    // ---- main GEMM: 2x2 warps, warp tile 32(j) x 32(ab) ----
    const int mw = wid >> 1;
    const int nw = wid & 1;
    const int rbase = mw * 32;
    const int cbase = nw * 32;

    float d[8][4];
    #pragma unroll
    for (int x = 0; x < 8; x++)
        #pragma unroll
        for (int c = 0; c < 4; c++)
            d[x][c] = 0.0f;

    #pragma unroll
    for (int kt = 0; kt < 4; kt++) {
        const int kw0 = kt * 8 + tig;

        uint32_t a[2][4];
        #pragma unroll
        for (int mt = 0; mt < 2; mt++) {
            const int r0 = rbase + mt * 16 + g;
            a[mt][0] = As32[r0 * ASW + kw0];
            a[mt][1] = As32[(r0 + 8) * ASW + kw0];
            a[mt][2] = As32[r0 * ASW + kw0 + 4];
            a[mt][3] = As32[(r0 + 8) * ASW + kw0 + 4];
        }

        uint32_t b[4][2];
        #pragma unroll
        for (int nt = 0; nt < 4; nt++) {
            const int col = cbase + nt * 8 + g;
            b[nt][0] = Bt32[col * BSW + kw0];
            b[nt][1] = Bt32[col * BSW + kw0 + 4];
        }

        #pragma unroll
        for (int mt = 0; mt < 2; mt++)
            #pragma unroll
            for (int nt = 0; nt < 4; nt++)
                mma_bf16(d[mt * 4 + nt], a[mt], b[nt]);
    }

    __syncthreads();   // staging smem dead; reuse as delta[2][2048]

    // ---- scatter fragments into delta (XOR-swizzled) ----
    // row = a_loc (= nw), col = j*32 + bb, word = row*2048 + (col ^ ((j&7)<<2))
    #pragma unroll
    for (int mt = 0; mt < 2; mt++) {
        const int jA = rbase + mt * 16 + g;    // 0..63
        const int jB = jA + 8;
        #pragma unroll
        for (int nt = 0; nt < 4; nt++) {
            const int ab = cbase + nt * 8 + 2 * tig;   // 0..63
            const int aa = ab >> 5;                    // = nw
            const int bb = ab & 31;
            const float* dd = d[mt * 4 + nt];

            const int wA = aa * 2048 + ((jA * 32 + bb) ^ ((jA & 7) << 2));
            *(float2*)&delta[wA] = make_float2(dd[0], dd[1]);
            const int wB = aa * 2048 + ((jB * 32 + bb) ^ ((jB & 7) << 2));
            *(float2*)&delta[wB] = make_float2(dd[2], dd[3]);
        }
    }
    __syncthreads();

    // ---- coalesced epilogue: 2 rows x 2048 cols ----
    #pragma unroll
    for (int it = 0; it < 8; it++) {
        const int idx = tid + it * 128;        // 0..1023 float4 slots
        const int r   = idx >> 9;              // 0/1
        const int cc  = (idx & 511) * 4;
        const int j   = cc >> 5;
        const int sw  = cc ^ ((j & 7) << 2);

        const int row_g = by * 32 + bx * 2 + r;
        const size_t off = (size_t)row_g * 2048 + cc;

        const float4 wv = *(const float4*)(weights + off);
        const float4 dv = *(const float4*)&delta[r * 2048 + sw];
        float4 ov;
        ov.x = wv.x + dv.x;
        ov.y = wv.y + dv.y;
        ov.z = wv.z + dv.z;
        ov.w = wv.w + dv.w;
        *(float4*)(out + off) = ov;
    }
}

extern "C" void kernel_launch(void* const* d_in, const int* in_sizes, int n_in,
                              void* d_out, int out_size)
{
    const float* weights = (const float*)d_in[0];
    const float* pos     = (const float*)d_in[1];
    const float* pw      = (const float*)d_in[2];
    const float* ph      = (const float*)d_in[3];
    float* out           = (float*)d_out;

    dim3 grid(16, 64);   // ab-blocks x i-rows = 1024 CTAs (single wave @ occ 8)
    dim3 block(128);
    splopa_mma_kernel<<<grid, block>>>(weights, pos, pw, ph, out);
}